// round 10
// baseline (speedup 1.0000x reference)
#include <cuda_runtime.h>
#include <cstdint>

// out[n] = realism(std(chunks[n])) + 0.15 + 0.2*cos(chunks[n,:10,:], prev[118:,:])
// chunks: [4096,128,64] f32 (2048 float4/chunk), prev: [128,64] f32, out: [4096] f32
//
// R2 architecture (batched LDG, one CTA per chunk) at 8 CTAs/SM:
// launch_bounds(256,8) + packed f32x2 accumulators keep regs <= 32,
// cutting the grid from 5.5 waves to 3.5 (fewer wave-transition drains).

__device__ __forceinline__ void fma2(unsigned long long& acc, unsigned long long a, unsigned long long b) {
    asm("fma.rn.f32x2 %0, %1, %2, %0;" : "+l"(acc) : "l"(a), "l"(b));
}
__device__ __forceinline__ void add2(unsigned long long& acc, unsigned long long a) {
    asm("add.rn.f32x2 %0, %0, %1;" : "+l"(acc) : "l"(a));
}
__device__ __forceinline__ float hsum2(unsigned long long v) {
    float lo, hi;
    asm("mov.b64 {%0,%1}, %2;" : "=f"(lo), "=f"(hi) : "l"(v));
    return lo + hi;
}

__global__ __launch_bounds__(256, 8) void chunk_ranker_kernel(
    const float* __restrict__ chunks,
    const float* __restrict__ prev,
    float* __restrict__ out)
{
    const int n = blockIdx.x;
    const int t = threadIdx.x;
    const ulonglong2* base = reinterpret_cast<const ulonglong2*>(chunks + (size_t)n * 8192);
    const ulonglong2* ctx  = reinterpret_cast<const ulonglong2*>(prev + 118 * 64); // 160 float4

    unsigned long long sum2 = 0ull, sq2 = 0ull;
    unsigned long long dot2 = 0ull, ssq2 = 0ull, csq2 = 0ull;

    // i = 0 covers float4 idx [0,256): prefix rows (idx<160) handled here.
    {
        ulonglong2 v = __ldg(&base[t]);
        add2(sum2, v.x); add2(sum2, v.y);
        fma2(sq2, v.x, v.x); fma2(sq2, v.y, v.y);
        if (t < 160) {
            ulonglong2 c = __ldg(&ctx[t]);
            fma2(dot2, v.x, c.x); fma2(dot2, v.y, c.y);
            fma2(ssq2, v.x, v.x); fma2(ssq2, v.y, v.y);
            fma2(csq2, c.x, c.x); fma2(csq2, c.y, c.y);
        }
    }
    #pragma unroll
    for (int i = 1; i < 8; i++) {
        ulonglong2 v = __ldg(&base[t + 256 * i]);
        add2(sum2, v.x); add2(sum2, v.y);
        fma2(sq2, v.x, v.x); fma2(sq2, v.y, v.y);
    }

    float sum = hsum2(sum2);
    float sq  = hsum2(sq2);
    float dot = hsum2(dot2);
    float ssq = hsum2(ssq2);
    float csq = hsum2(csq2);

    #pragma unroll
    for (int off = 16; off > 0; off >>= 1) {
        sum += __shfl_down_sync(0xffffffffu, sum, off);
        sq  += __shfl_down_sync(0xffffffffu, sq,  off);
        dot += __shfl_down_sync(0xffffffffu, dot, off);
        ssq += __shfl_down_sync(0xffffffffu, ssq, off);
        csq += __shfl_down_sync(0xffffffffu, csq, off);
    }

    __shared__ float red[8][5];
    const int wid = t >> 5, lid = t & 31;
    if (lid == 0) {
        red[wid][0] = sum; red[wid][1] = sq; red[wid][2] = dot;
        red[wid][3] = ssq; red[wid][4] = csq;
    }
    __syncthreads();

    if (t == 0) {
        float S = 0.f, Q = 0.f, D = 0.f, SS = 0.f, CS = 0.f;
        #pragma unroll
        for (int w = 0; w < 8; w++) {
            S += red[w][0]; Q += red[w][1]; D += red[w][2];
            SS += red[w][3]; CS += red[w][4];
        }
        const float M = 8192.0f;
        float var = (Q - S * S / M) / (M - 1.0f);
        float sd = sqrtf(fmaxf(var, 0.0f));

        float realism;
        if (sd < 0.01f)      realism = sd * 10.0f;
        else if (sd > 0.5f)  realism = 0.5f / sd;
        else                 realism = 1.0f - fabsf(sd - 0.1f);

        float denom = fmaxf(sqrtf(SS) * sqrtf(CS), 1e-8f);
        float boundary = D / denom;

        out[n] = realism + 0.3f * 0.5f + 0.2f * boundary;
    }
}

extern "C" void kernel_launch(void* const* d_in, const int* in_sizes, int n_in,
                              void* d_out, int out_size)
{
    const float* chunks = (const float*)d_in[0];   // [4096,128,64] f32
    // d_in[1] = regime_probs [9] — unused (constant consistency 0.5)
    const float* prev = (const float*)d_in[2];     // [128,64] f32
    float* out = (float*)d_out;                    // [4096] f32

    const int n_chunks = in_sizes[0] / (128 * 64); // 4096
    chunk_ranker_kernel<<<n_chunks, 256>>>(chunks, prev, out);
}